// round 15
// baseline (speedup 1.0000x reference)
#include <cuda_runtime.h>
#include <cuda_bf16.h>
#include <cstdint>
#include <cstdio>

// ---------------- problem constants ----------------
#define NN      100000
#define EE      1600000
#define NF      128
#define NCLASS  40
#define BN_EPS  1e-5f

// ---------------- device scratch ----------------
__device__ int   g_flag[1];
__device__ int   g_deg[NN];
__device__ int   g_tmp[NN];
__device__ int   g_bsum[256];
__device__ int   g_boff[256];
__device__ int   g_off[NN + 1];
__device__ int   g_cur[NN];
__device__ int   g_csr[EE];

__device__ float g_agg [NN * NF];
__device__ float g_h1  [NN * NF];
__device__ float g_h2  [NN * NF];
__device__ float g_p   [NN * 80];
__device__ float g_oraw[NN * NCLASS];
__device__ float g_stats[256];
__device__ float g_scale[128];
__device__ float g_shift[128];

// bf16 hi/lo weights, [j=output col][K] k-major
__device__ __nv_bfloat16 g_w1rh[128 * 128], g_w1rl[128 * 128];
__device__ __nv_bfloat16 g_w1lh[128 * 128], g_w1ll[128 * 128];
__device__ __nv_bfloat16 g_wxh [128 * 256], g_wxl [128 * 256];
__device__ __nv_bfloat16 g_w2h [128 * 128], g_w2l [128 * 128];

// ---------------- edge-index dtype detect ----------------
__global__ void detect_dtype_kernel(const void* p, int E, int n_nodes) {
    if (threadIdx.x == 0 && blockIdx.x == 0) {
        const long long* q = (const long long*)p;
        int m = E < 512 ? E : 512;
        int bad = 0;
        for (int i = 0; i < m; i++) {
            long long v = q[i];
            if (v < 0 || v >= (long long)n_nodes) bad = 1;
        }
        g_flag[0] = bad;
    }
}

__global__ void zero_int_kernel(int* p, int n) {
    for (int i = blockIdx.x * blockDim.x + threadIdx.x; i < n;
         i += gridDim.x * blockDim.x) p[i] = 0;
}

__global__ void count_deg_direct(const void* p, int E) {
    int is32 = g_flag[0];
    for (int e = blockIdx.x * blockDim.x + threadIdx.x; e < E;
         e += gridDim.x * blockDim.x) {
        int v = is32 ? ((const int*)p)[E + e]
                     : (int)((const long long*)p)[E + e];
        atomicAdd(&g_deg[v], 1);
    }
}

// ---------------- CSR build ----------------
__global__ void scan1_kernel(int n) {
    __shared__ int sh[512];
    int i = blockIdx.x * 512 + threadIdx.x;
    int v = (i < n) ? g_deg[i] : 0;
    sh[threadIdx.x] = v;
    __syncthreads();
    #pragma unroll
    for (int s = 1; s < 512; s <<= 1) {
        int t = (threadIdx.x >= s) ? sh[threadIdx.x - s] : 0;
        __syncthreads();
        sh[threadIdx.x] += t;
        __syncthreads();
    }
    if (i < n) g_tmp[i] = sh[threadIdx.x];
    if (threadIdx.x == 511) g_bsum[blockIdx.x] = sh[511];
}

__global__ void scan2_kernel(int nb) {
    __shared__ int sh[256];
    int v = (threadIdx.x < nb) ? g_bsum[threadIdx.x] : 0;
    sh[threadIdx.x] = v;
    __syncthreads();
    #pragma unroll
    for (int s = 1; s < 256; s <<= 1) {
        int t = (threadIdx.x >= s) ? sh[threadIdx.x - s] : 0;
        __syncthreads();
        sh[threadIdx.x] += t;
        __syncthreads();
    }
    if (threadIdx.x < nb) g_boff[threadIdx.x] = sh[threadIdx.x] - v;
}

__global__ void scan3_kernel(int n) {
    for (int i = blockIdx.x * blockDim.x + threadIdx.x; i < n;
         i += gridDim.x * blockDim.x) {
        int incl = g_tmp[i] + g_boff[i >> 9];
        int excl = incl - g_deg[i];
        g_off[i] = excl;
        g_cur[i] = excl;
        if (i == n - 1) g_off[n] = incl;
    }
}

__global__ void fill_csr_direct(const void* p, int E) {
    int is32 = g_flag[0];
    for (int e = blockIdx.x * blockDim.x + threadIdx.x; e < E;
         e += gridDim.x * blockDim.x) {
        int d, s;
        if (is32) {
            d = ((const int*)p)[E + e];
            s = ((const int*)p)[e];
        } else {
            d = (int)((const long long*)p)[E + e];
            s = (int)((const long long*)p)[e];
        }
        int pos = atomicAdd(&g_cur[d], 1);
        g_csr[pos] = s;
    }
}

// ---------------- weight prep: bf16 hi/lo split ----------------
__device__ __forceinline__ void bf16_split(float w, __nv_bfloat16& h, __nv_bfloat16& l) {
    h = __float2bfloat16(w);
    l = __float2bfloat16(w - __bfloat162float(h));
}

__global__ void prep_w_single(const float* __restrict__ W,
                              __nv_bfloat16* __restrict__ Oh,
                              __nv_bfloat16* __restrict__ Ol) {
    for (int idx = blockIdx.x * blockDim.x + threadIdx.x; idx < 128 * 128;
         idx += gridDim.x * blockDim.x) {
        __nv_bfloat16 h, l;
        bf16_split(W[idx], h, l);
        Oh[idx] = h; Ol[idx] = l;
    }
}

__global__ void prep_w_dual(const float* __restrict__ Wl, const float* __restrict__ Wr,
                            __nv_bfloat16* __restrict__ Oh,
                            __nv_bfloat16* __restrict__ Ol) {
    for (int idx = blockIdx.x * blockDim.x + threadIdx.x; idx < 128 * 256;
         idx += gridDim.x * blockDim.x) {
        int j = idx >> 8, k = idx & 255;
        float w = (k < 128) ? Wl[j * 128 + k] : Wr[j * 128 + (k - 128)];
        __nv_bfloat16 h, l;
        bf16_split(w, h, l);
        Oh[idx] = h; Ol[idx] = l;
    }
}

__global__ void prep_w2_bf16(const float* __restrict__ W2l,
                             const float* __restrict__ W2r) {
    for (int idx = blockIdx.x * blockDim.x + threadIdx.x; idx < 128 * 128;
         idx += gridDim.x * blockDim.x) {
        int j = idx >> 7, k = idx & 127;
        float w = 0.f;
        if (j < 40)      w = W2l[j * 128 + k];
        else if (j < 80) w = W2r[(j - 40) * 128 + k];
        __nv_bfloat16 h, l;
        bf16_split(w, h, l);
        g_w2h[idx] = h; g_w2l[idx] = l;
    }
}

// ---------------- mean aggregation, warp-per-node, float4, MLP8 ----------------
__global__ __launch_bounds__(256)
void agg_mean128_kernel(const float* __restrict__ X,
                        float* __restrict__ OUT, int n) {
    int warp = threadIdx.x >> 5;
    int lane = threadIdx.x & 31;
    int node = blockIdx.x * 8 + warp;
    if (node >= n) return;
    const float4* X4 = (const float4*)X;
    int s0 = g_off[node], s1 = g_off[node + 1];
    float4 a0 = make_float4(0.f, 0.f, 0.f, 0.f);
    float4 a1 = make_float4(0.f, 0.f, 0.f, 0.f);
    for (int base = s0; base < s1; base += 32) {
        int c = s1 - base; if (c > 32) c = 32;
        int nbv = (lane < c) ? g_csr[base + lane] : 0;
        int j = 0;
        for (; j + 8 <= c; j += 8) {
            int v0 = __shfl_sync(0xffffffffu, nbv, j);
            int v1 = __shfl_sync(0xffffffffu, nbv, j + 1);
            int v2 = __shfl_sync(0xffffffffu, nbv, j + 2);
            int v3 = __shfl_sync(0xffffffffu, nbv, j + 3);
            int v4 = __shfl_sync(0xffffffffu, nbv, j + 4);
            int v5 = __shfl_sync(0xffffffffu, nbv, j + 5);
            int v6 = __shfl_sync(0xffffffffu, nbv, j + 6);
            int v7 = __shfl_sync(0xffffffffu, nbv, j + 7);
            float4 x0 = X4[(size_t)v0 * 32 + lane];
            float4 x1 = X4[(size_t)v1 * 32 + lane];
            float4 x2 = X4[(size_t)v2 * 32 + lane];
            float4 x3 = X4[(size_t)v3 * 32 + lane];
            float4 x4 = X4[(size_t)v4 * 32 + lane];
            float4 x5 = X4[(size_t)v5 * 32 + lane];
            float4 x6 = X4[(size_t)v6 * 32 + lane];
            float4 x7 = X4[(size_t)v7 * 32 + lane];
            a0.x += (x0.x + x1.x) + (x2.x + x3.x);
            a0.y += (x0.y + x1.y) + (x2.y + x3.y);
            a0.z += (x0.z + x1.z) + (x2.z + x3.z);
            a0.w += (x0.w + x1.w) + (x2.w + x3.w);
            a1.x += (x4.x + x5.x) + (x6.x + x7.x);
            a1.y += (x4.y + x5.y) + (x6.y + x7.y);
            a1.z += (x4.z + x5.z) + (x6.z + x7.z);
            a1.w += (x4.w + x5.w) + (x6.w + x7.w);
        }
        for (; j < c; j++) {
            int v = __shfl_sync(0xffffffffu, nbv, j);
            float4 x = X4[(size_t)v * 32 + lane];
            a0.x += x.x; a0.y += x.y; a0.z += x.z; a0.w += x.w;
        }
    }
    int deg = s1 - s0;
    float inv = deg > 0 ? 1.f / (float)deg : 0.f;
    float4 acc;
    acc.x = (a0.x + a1.x) * inv;
    acc.y = (a0.y + a1.y) * inv;
    acc.z = (a0.z + a1.z) * inv;
    acc.w = (a0.w + a1.w) * inv;
    ((float4*)OUT)[(size_t)node * 32 + lane] = acc;
}

// ---------------- conv2: agg 40-wide + combine + bias + fused BN2 stats ----------------
__global__ __launch_bounds__(256)
void agg40_kernel(const float* __restrict__ b2, int n) {
    __shared__ float s_sum[40];
    __shared__ float s_sq[40];
    int tid = threadIdx.x;
    if (tid < 40) { s_sum[tid] = 0.f; s_sq[tid] = 0.f; }
    __syncthreads();

    int warp = tid >> 5;
    int lane = tid & 31;
    int node = blockIdx.x * 8 + warp;
    if (node < n) {
        const float4* P4 = (const float4*)g_p;
        int s0 = g_off[node], s1 = g_off[node + 1];
        float4 acc = make_float4(0.f, 0.f, 0.f, 0.f);
        for (int base = s0; base < s1; base += 32) {
            int c = s1 - base; if (c > 32) c = 32;
            int nbv = (lane < c) ? g_csr[base + lane] : 0;
            int j = 0;
            for (; j + 4 <= c; j += 4) {
                int v0 = __shfl_sync(0xffffffffu, nbv, j);
                int v1 = __shfl_sync(0xffffffffu, nbv, j + 1);
                int v2 = __shfl_sync(0xffffffffu, nbv, j + 2);
                int v3 = __shfl_sync(0xffffffffu, nbv, j + 3);
                if (lane < 10) {
                    float4 x0 = P4[(size_t)v0 * 20 + lane];
                    float4 x1 = P4[(size_t)v1 * 20 + lane];
                    float4 x2 = P4[(size_t)v2 * 20 + lane];
                    float4 x3 = P4[(size_t)v3 * 20 + lane];
                    acc.x += (x0.x + x1.x) + (x2.x + x3.x);
                    acc.y += (x0.y + x1.y) + (x2.y + x3.y);
                    acc.z += (x0.z + x1.z) + (x2.z + x3.z);
                    acc.w += (x0.w + x1.w) + (x2.w + x3.w);
                }
            }
            for (; j < c; j++) {
                int v = __shfl_sync(0xffffffffu, nbv, j);
                if (lane < 10) {
                    float4 x = P4[(size_t)v * 20 + lane];
                    acc.x += x.x; acc.y += x.y; acc.z += x.z; acc.w += x.w;
                }
            }
        }
        if (lane < 10) {
            int deg = s1 - s0;
            float inv = deg > 0 ? 1.f / (float)deg : 0.f;
            float4 r  = P4[(size_t)node * 20 + 10 + lane];
            float4 bb = ((const float4*)b2)[lane];
            float4 o;
            o.x = acc.x * inv + r.x + bb.x;
            o.y = acc.y * inv + r.y + bb.y;
            o.z = acc.z * inv + r.z + bb.z;
            o.w = acc.w * inv + r.w + bb.w;
            ((float4*)g_oraw)[(size_t)node * 10 + lane] = o;
            int c0 = lane * 4;
            atomicAdd(&s_sum[c0 + 0], o.x); atomicAdd(&s_sq[c0 + 0], o.x * o.x);
            atomicAdd(&s_sum[c0 + 1], o.y); atomicAdd(&s_sq[c0 + 1], o.y * o.y);
            atomicAdd(&s_sum[c0 + 2], o.z); atomicAdd(&s_sq[c0 + 2], o.z * o.z);
            atomicAdd(&s_sum[c0 + 3], o.w); atomicAdd(&s_sq[c0 + 3], o.w * o.w);
        }
    }
    __syncthreads();
    if (tid < 40) {
        atomicAdd(&g_stats[tid], s_sum[tid]);
        atomicAdd(&g_stats[128 + tid], s_sq[tid]);
    }
}

// ---------------- bf16 mma.sync GEMM with hi/lo split ----------------
#define SSTR 40

__device__ __forceinline__ void mma16816(float* c, const uint32_t* a,
                                         uint32_t b0, uint32_t b1) {
    asm volatile(
        "mma.sync.aligned.m16n8k16.row.col.f32.bf16.bf16.f32 "
        "{%0,%1,%2,%3}, {%4,%5,%6,%7}, {%8,%9}, {%0,%1,%2,%3};"
        : "+f"(c[0]), "+f"(c[1]), "+f"(c[2]), "+f"(c[3])
        : "r"(a[0]), "r"(a[1]), "r"(a[2]), "r"(a[3]), "r"(b0), "r"(b1));
}

// per-nt inner body as a macro so the full-unroll and clamped paths share code
#define GEMM_NT_BODY(nt)                                              \
    do {                                                              \
        int bn = wcol + 8 * (nt) + tg;                                \
        int ob = bn * SSTR + kb + t4 * 2;                             \
        uint32_t bh0 = *(const uint32_t*)&Bsh[ob];                    \
        uint32_t bh1 = *(const uint32_t*)&Bsh[ob + 8];                \
        uint32_t bl0 = *(const uint32_t*)&Bsl[ob];                    \
        uint32_t bl1 = *(const uint32_t*)&Bsl[ob + 8];                \
        _Pragma("unroll")                                             \
        for (int mt = 0; mt < 2; mt++) {                              \
            mma16816(acc[mt][nt], ah[mt], bh0, bh1);                  \
            mma16816(acc[mt][nt], al[mt], bh0, bh1);                  \
            mma16816(acc[mt][nt], ah[mt], bl0, bl1);                  \
        }                                                             \
    } while (0)

__global__ __launch_bounds__(256, 2)
void gemm_mma_kernel(const float* __restrict__ A1, const float* __restrict__ A2,
                     const __nv_bfloat16* __restrict__ Bh,
                     const __nv_bfloat16* __restrict__ Bl,
                     const float* __restrict__ bias, const float* __restrict__ addin,
                     float* __restrict__ C, int M, int K, int ncol,
                     int ldc, int relu, int bnA, int do_stats) {
    __shared__ __align__(16) __nv_bfloat16 Ash[128 * SSTR];
    __shared__ __align__(16) __nv_bfloat16 Asl[128 * SSTR];
    __shared__ __align__(16) __nv_bfloat16 Bsh[128 * SSTR];
    __shared__ __align__(16) __nv_bfloat16 Bsl[128 * SSTR];
    __shared__ float s_sum[128];
    __shared__ float s_sq[128];

    const int tid  = threadIdx.x;
    const int wid  = tid >> 5;
    const int lane = tid & 31;
    const int tg   = lane >> 2;
    const int t4   = lane & 3;
    const int wrow = (wid & 3) * 32;
    const int wcol = (wid >> 2) * 64;
    const int row0 = blockIdx.x * 128;
    // live n-subtiles for this warp (8 when the warp's whole 64-col span < ncol)
    const bool nt_full = (wcol + 64) <= ncol;
    const int  nt_max  = nt_full ? 8 : ((ncol > wcol) ? ((ncol - wcol + 7) >> 3) : 0);

    float acc[2][8][4];
    #pragma unroll
    for (int mt = 0; mt < 2; mt++)
        #pragma unroll
        for (int nt = 0; nt < 8; nt++)
            #pragma unroll
            for (int i = 0; i < 4; i++) acc[mt][nt][i] = 0.f;

    const int sr   = tid >> 1;
    const int shf  = (tid & 1) * 16;

    for (int k0 = 0; k0 < K; k0 += 32) {
        {
            int rg = row0 + sr;
            #pragma unroll
            for (int i = 0; i < 4; i++) {
                int kg = k0 + shf + i * 4;
                const float* Ap = (kg < 128) ? A1 : A2;
                int kl = kg & 127;
                float4 v = make_float4(0.f, 0.f, 0.f, 0.f);
                if (rg < M) v = *(const float4*)&Ap[(size_t)rg * 128 + kl];
                if (bnA) {
                    float4 sc = *(const float4*)&g_scale[kg];
                    float4 sh = *(const float4*)&g_shift[kg];
                    v.x = fmaxf(v.x * sc.x + sh.x, 0.f);
                    v.y = fmaxf(v.y * sc.y + sh.y, 0.f);
                    v.z = fmaxf(v.z * sc.z + sh.z, 0.f);
                    v.w = fmaxf(v.w * sc.w + sh.w, 0.f);
                }
                __nv_bfloat16 hx = __float2bfloat16(v.x);
                __nv_bfloat16 hy = __float2bfloat16(v.y);
                __nv_bfloat16 hz = __float2bfloat16(v.z);
                __nv_bfloat16 hw = __float2bfloat16(v.w);
                __nv_bfloat16 lx = __float2bfloat16(v.x - __bfloat162float(hx));
                __nv_bfloat16 ly = __float2bfloat16(v.y - __bfloat162float(hy));
                __nv_bfloat16 lz = __float2bfloat16(v.z - __bfloat162float(hz));
                __nv_bfloat16 lw = __float2bfloat16(v.w - __bfloat162float(hw));
                uint32_t* dh = (uint32_t*)&Ash[sr * SSTR + shf + i * 4];
                uint32_t* dl = (uint32_t*)&Asl[sr * SSTR + shf + i * 4];
                dh[0] = (uint32_t)__bfloat16_as_ushort(hx) |
                        ((uint32_t)__bfloat16_as_ushort(hy) << 16);
                dh[1] = (uint32_t)__bfloat16_as_ushort(hz) |
                        ((uint32_t)__bfloat16_as_ushort(hw) << 16);
                dl[0] = (uint32_t)__bfloat16_as_ushort(lx) |
                        ((uint32_t)__bfloat16_as_ushort(ly) << 16);
                dl[1] = (uint32_t)__bfloat16_as_ushort(lz) |
                        ((uint32_t)__bfloat16_as_ushort(lw) << 16);
            }
        }
        {
            const uint4* sh_ = (const uint4*)&Bh[(size_t)sr * K + k0 + shf];
            const uint4* sl_ = (const uint4*)&Bl[(size_t)sr * K + k0 + shf];
            uint4* dh = (uint4*)&Bsh[sr * SSTR + shf];
            uint4* dl = (uint4*)&Bsl[sr * SSTR + shf];
            dh[0] = sh_[0]; dh[1] = sh_[1];
            dl[0] = sl_[0]; dl[1] = sl_[1];
        }
        __syncthreads();

        #pragma unroll
        for (int s = 0; s < 2; s++) {
            const int kb = s * 16;
            uint32_t ah[2][4], al[2][4];
            #pragma unroll
            for (int mt = 0; mt < 2; mt++) {
                int r = wrow + 16 * mt + tg;
                int o0 = r * SSTR + kb + t4 * 2;
                int o1 = (r + 8) * SSTR + kb + t4 * 2;
                ah[mt][0] = *(const uint32_t*)&Ash[o0];
                ah[mt][1] = *(const uint32_t*)&Ash[o1];
                ah[mt][2] = *(const uint32_t*)&Ash[o0 + 8];
                ah[mt][3] = *(const uint32_t*)&Ash[o1 + 8];
                al[mt][0] = *(const uint32_t*)&Asl[o0];
                al[mt][1] = *(const uint32_t*)&Asl[o1];
                al[mt][2] = *(const uint32_t*)&Asl[o0 + 8];
                al[mt][3] = *(const uint32_t*)&Asl[o1 + 8];
            }
            if (nt_full) {
                #pragma unroll
                for (int nt = 0; nt < 8; nt++) GEMM_NT_BODY(nt);
            } else {
                for (int nt = 0; nt < nt_max; nt++) GEMM_NT_BODY(nt);
            }
        }
        __syncthreads();
    }

    // ---- epilogue ----
    float colsum[8][2], colsq[8][2];
    #pragma unroll
    for (int nt = 0; nt < 8; nt++) {
        colsum[nt][0] = 0.f; colsum[nt][1] = 0.f;
        colsq[nt][0] = 0.f;  colsq[nt][1] = 0.f;
    }

    #pragma unroll
    for (int mt = 0; mt < 2; mt++) {
        #pragma unroll
        for (int half = 0; half < 2; half++) {
            int rg = row0 + wrow + 16 * mt + tg + 8 * half;
            bool rok = rg < M;
            #pragma unroll
            for (int nt = 0; nt < 8; nt++) {
                int c = wcol + 8 * nt + 2 * t4;
                if (c >= ncol) continue;
                float v0 = acc[mt][nt][2 * half + 0];
                float v1 = acc[mt][nt][2 * half + 1];
                if (bias) {
                    float2 bb = *(const float2*)&bias[c];
                    v0 += bb.x; v1 += bb.y;
                }
                if (rok) {
                    if (addin) {
                        float2 aa = *(const float2*)&addin[(size_t)rg * ldc + c];
                        v0 += aa.x; v1 += aa.y;
                    }
                    if (relu) { v0 = fmaxf(v0, 0.f); v1 = fmaxf(v1, 0.f); }
                    *(float2*)&C[(size_t)rg * ldc + c] = make_float2(v0, v1);
                    if (do_stats) {
                        colsum[nt][0] += v0; colsum[nt][1] += v1;
                        colsq[nt][0] += v0 * v0; colsq[nt][1] += v1 * v1;
                    }
                }
            }
        }
    }

    if (do_stats) {
        if (tid < 128) { s_sum[tid] = 0.f; s_sq[tid] = 0.f; }
        __syncthreads();
        #pragma unroll
        for (int nt = 0; nt < 8; nt++) {
            int c = wcol + 8 * nt + 2 * t4;
            if (c < ncol) {
                atomicAdd(&s_sum[c],     colsum[nt][0]);
                atomicAdd(&s_sum[c + 1], colsum[nt][1]);
                atomicAdd(&s_sq[c],      colsq[nt][0]);
                atomicAdd(&s_sq[c + 1],  colsq[nt][1]);
            }
        }
        __syncthreads();
        if (tid < 128) {
            atomicAdd(&g_stats[tid], s_sum[tid]);
            atomicAdd(&g_stats[128 + tid], s_sq[tid]);
        }
    }
}

// ---------------- BatchNorm helpers ----------------
__global__ void zero_stats_kernel() {
    if (threadIdx.x < 256) g_stats[threadIdx.x] = 0.f;
}

// reads stats, writes scale/shift, then zeroes stats for the next use
__global__ void bn_finalize_kernel(const float* __restrict__ gamma,
                                   const float* __restrict__ beta,
                                   int F, float invM) {
    int c = threadIdx.x;
    if (c < F) {
        float mu  = g_stats[c] * invM;
        float var = g_stats[128 + c] * invM - mu * mu;
        float sc  = gamma[c] * rsqrtf(var + BN_EPS);
        g_scale[c] = sc;
        g_shift[c] = beta[c] - mu * sc;
        g_stats[c] = 0.f;
        g_stats[128 + c] = 0.f;
    }
}

__global__ void bn_apply_kernel(const float* __restrict__ X, float* __restrict__ Y,
                                int total, int F) {
    for (int i = blockIdx.x * blockDim.x + threadIdx.x; i < total;
         i += gridDim.x * blockDim.x) {
        int c = i % F;
        Y[i] = X[i] * g_scale[c] + g_shift[c];
    }
}

// ---------------- launcher ----------------
extern "C" void kernel_launch(void* const* d_in, const int* in_sizes, int n_in,
                              void* d_out, int out_size) {
    const float* x   = (const float*)d_in[0];
    const void*  ei  = d_in[1];
    const float* W1l = (const float*)d_in[2];
    const float* b1  = (const float*)d_in[3];
    const float* W1r = (const float*)d_in[4];
    const float* Wxl = (const float*)d_in[5];
    const float* bx  = (const float*)d_in[6];
    const float* Wxr = (const float*)d_in[7];
    const float* W2l = (const float*)d_in[8];
    const float* b2  = (const float*)d_in[9];
    const float* W2r = (const float*)d_in[10];
    const float* g3  = (const float*)d_in[11];
    const float* be3 = (const float*)d_in[12];
    const float* g2  = (const float*)d_in[13];
    const float* be2 = (const float*)d_in[14];
    float* out = (float*)d_out;

    const int N    = in_sizes[0] / NF;
    const int twoE = in_sizes[1];
    const int E    = twoE / 2;

    float *p_agg, *p_h1, *p_h2, *p_p, *p_oraw;
    int   *p_deg;
    __nv_bfloat16 *w1rh, *w1rl, *w1lh, *w1ll, *wxh, *wxl, *w2h, *w2l;
    cudaGetSymbolAddress((void**)&p_agg,  g_agg);
    cudaGetSymbolAddress((void**)&p_h1,   g_h1);
    cudaGetSymbolAddress((void**)&p_h2,   g_h2);
    cudaGetSymbolAddress((void**)&p_p,    g_p);
    cudaGetSymbolAddress((void**)&p_oraw, g_oraw);
    cudaGetSymbolAddress((void**)&p_deg,  g_deg);
    cudaGetSymbolAddress((void**)&w1rh, g_w1rh); cudaGetSymbolAddress((void**)&w1rl, g_w1rl);
    cudaGetSymbolAddress((void**)&w1lh, g_w1lh); cudaGetSymbolAddress((void**)&w1ll, g_w1ll);
    cudaGetSymbolAddress((void**)&wxh,  g_wxh);  cudaGetSymbolAddress((void**)&wxl,  g_wxl);
    cudaGetSymbolAddress((void**)&w2h,  g_w2h);  cudaGetSymbolAddress((void**)&w2l,  g_w2l);

    const int nb = (N + 511) / 512;
    const int gemm_blocks = (N + 127) / 128;
    const int agg_blocks  = (N + 7) / 8;

    cudaStream_t s2;
    cudaStreamCreateWithFlags(&s2, cudaStreamNonBlocking);
    cudaEvent_t evA, evB;
    cudaEventCreateWithFlags(&evA, cudaEventDisableTiming);
    cudaEventCreateWithFlags(&evB, cudaEventDisableTiming);

    // --- fork: CSR chain on s2 ---
    detect_dtype_kernel<<<1, 32>>>(ei, E, N);
    cudaEventRecord(evA, 0);
    cudaStreamWaitEvent(s2, evA, 0);

    zero_int_kernel<<<512, 256, 0, s2>>>(p_deg, N);
    count_deg_direct<<<2048, 256, 0, s2>>>(ei, E);
    scan1_kernel<<<nb, 512, 0, s2>>>(N);
    scan2_kernel<<<1, 256, 0, s2>>>(nb);
    scan3_kernel<<<512, 256, 0, s2>>>(N);
    fill_csr_direct<<<2048, 256, 0, s2>>>(ei, E);
    cudaEventRecord(evB, s2);

    // --- main: weight prep + conv1a (x @ W1r^T + b1) + first stats zero ---
    prep_w_single<<<64, 256>>>(W1r, w1rh, w1rl);
    zero_stats_kernel<<<1, 256>>>();
    gemm_mma_kernel<<<gemm_blocks, 256>>>(x, x, w1rh, w1rl, b1, nullptr,
                                          p_h1, N, 128, 128, 128, 0, 0, 0);
    prep_w_single<<<64, 256>>>(W1l, w1lh, w1ll);
    prep_w_dual<<<128, 256>>>(Wxl, Wxr, wxh, wxl);
    prep_w2_bf16<<<64, 256>>>(W2l, W2r);

    // --- join CSR ---
    cudaStreamWaitEvent(0, evB, 0);

    // conv1 part 2: h1 = relu(agg @ W1l^T + h1)
    agg_mean128_kernel<<<agg_blocks, 256>>>(x, p_agg, N);
    gemm_mma_kernel<<<gemm_blocks, 256>>>(p_agg, p_agg, w1lh, w1ll, nullptr, p_h1,
                                          p_h1, N, 128, 128, 128, 1, 0, 0);

    // convx: h2 = concat(agg, h1) @ [Wxl|Wxr]^T + bx  (+BN3 stats fused)
    agg_mean128_kernel<<<agg_blocks, 256>>>(p_h1, p_agg, N);
    gemm_mma_kernel<<<gemm_blocks, 256>>>(p_agg, p_h1, wxh, wxl, bx, nullptr,
                                          p_h2, N, 256, 128, 128, 0, 0, 1);
    bn_finalize_kernel<<<1, 128>>>(g3, be3, 128, 1.f / (float)N);  // also zeroes stats

    // conv2 projection: P = BNrelu(h2) @ [W2l|W2r]^T  (bnA fused; nt-clamped)
    gemm_mma_kernel<<<gemm_blocks, 256>>>(p_h2, p_h2, w2h, w2l, nullptr, nullptr,
                                          p_p, N, 128, 80, 80, 0, 1, 0);
    // aggregate + combine + BN2 stats
    agg40_kernel<<<agg_blocks, 256>>>(b2, N);

    // BN2 -> output
    bn_finalize_kernel<<<1, 64>>>(g2, be2, NCLASS, 1.f / (float)N);
    bn_apply_kernel<<<2048, 256>>>(p_oraw, out, N * NCLASS, NCLASS);
}

// round 16
// speedup vs baseline: 1.4725x; 1.4725x over previous
#include <cuda_runtime.h>
#include <cuda_bf16.h>
#include <cstdint>
#include <cstdio>

// ---------------- problem constants ----------------
#define NN      100000
#define EE      1600000
#define NF      128
#define NCLASS  40
#define BN_EPS  1e-5f

// ---------------- device scratch ----------------
__device__ int   g_flag[1];
__device__ int   g_deg[NN];
__device__ int   g_tmp[NN];
__device__ int   g_bsum[256];
__device__ int   g_boff[256];
__device__ int   g_off[NN + 1];
__device__ int   g_cur[NN];
__device__ int   g_csr[EE];

__device__ float g_agg [NN * NF];
__device__ float g_h1  [NN * NF];
__device__ float g_h2  [NN * NF];
__device__ float g_p   [NN * 80];
__device__ float g_oraw[NN * NCLASS];
__device__ float g_stats[256];
__device__ float g_scale[128];
__device__ float g_shift[128];

// bf16 hi/lo weights, [j=output col][K] k-major
__device__ __nv_bfloat16 g_w1rh[128 * 128], g_w1rl[128 * 128];
__device__ __nv_bfloat16 g_w1lh[128 * 128], g_w1ll[128 * 128];
__device__ __nv_bfloat16 g_wxh [128 * 256], g_wxl [128 * 256];
__device__ __nv_bfloat16 g_w2h [128 * 128], g_w2l [128 * 128];

// ---------------- edge-index dtype detect ----------------
__global__ void detect_dtype_kernel(const void* p, int E, int n_nodes) {
    if (threadIdx.x == 0 && blockIdx.x == 0) {
        const long long* q = (const long long*)p;
        int m = E < 512 ? E : 512;
        int bad = 0;
        for (int i = 0; i < m; i++) {
            long long v = q[i];
            if (v < 0 || v >= (long long)n_nodes) bad = 1;
        }
        g_flag[0] = bad;
    }
}

__global__ void zero_int_kernel(int* p, int n) {
    for (int i = blockIdx.x * blockDim.x + threadIdx.x; i < n;
         i += gridDim.x * blockDim.x) p[i] = 0;
}

__global__ void count_deg_direct(const void* p, int E) {
    int is32 = g_flag[0];
    for (int e = blockIdx.x * blockDim.x + threadIdx.x; e < E;
         e += gridDim.x * blockDim.x) {
        int v = is32 ? ((const int*)p)[E + e]
                     : (int)((const long long*)p)[E + e];
        atomicAdd(&g_deg[v], 1);
    }
}

// ---------------- CSR build ----------------
__global__ void scan1_kernel(int n) {
    __shared__ int sh[512];
    int i = blockIdx.x * 512 + threadIdx.x;
    int v = (i < n) ? g_deg[i] : 0;
    sh[threadIdx.x] = v;
    __syncthreads();
    #pragma unroll
    for (int s = 1; s < 512; s <<= 1) {
        int t = (threadIdx.x >= s) ? sh[threadIdx.x - s] : 0;
        __syncthreads();
        sh[threadIdx.x] += t;
        __syncthreads();
    }
    if (i < n) g_tmp[i] = sh[threadIdx.x];
    if (threadIdx.x == 511) g_bsum[blockIdx.x] = sh[511];
}

__global__ void scan2_kernel(int nb) {
    __shared__ int sh[256];
    int v = (threadIdx.x < nb) ? g_bsum[threadIdx.x] : 0;
    sh[threadIdx.x] = v;
    __syncthreads();
    #pragma unroll
    for (int s = 1; s < 256; s <<= 1) {
        int t = (threadIdx.x >= s) ? sh[threadIdx.x - s] : 0;
        __syncthreads();
        sh[threadIdx.x] += t;
        __syncthreads();
    }
    if (threadIdx.x < nb) g_boff[threadIdx.x] = sh[threadIdx.x] - v;
}

__global__ void scan3_kernel(int n) {
    for (int i = blockIdx.x * blockDim.x + threadIdx.x; i < n;
         i += gridDim.x * blockDim.x) {
        int incl = g_tmp[i] + g_boff[i >> 9];
        int excl = incl - g_deg[i];
        g_off[i] = excl;
        g_cur[i] = excl;
        if (i == n - 1) g_off[n] = incl;
    }
}

__global__ void fill_csr_direct(const void* p, int E) {
    int is32 = g_flag[0];
    for (int e = blockIdx.x * blockDim.x + threadIdx.x; e < E;
         e += gridDim.x * blockDim.x) {
        int d, s;
        if (is32) {
            d = ((const int*)p)[E + e];
            s = ((const int*)p)[e];
        } else {
            d = (int)((const long long*)p)[E + e];
            s = (int)((const long long*)p)[e];
        }
        int pos = atomicAdd(&g_cur[d], 1);
        g_csr[pos] = s;
    }
}

// ---------------- weight prep: bf16 hi/lo split ----------------
__device__ __forceinline__ void bf16_split(float w, __nv_bfloat16& h, __nv_bfloat16& l) {
    h = __float2bfloat16(w);
    l = __float2bfloat16(w - __bfloat162float(h));
}

__global__ void prep_w_single(const float* __restrict__ W,
                              __nv_bfloat16* __restrict__ Oh,
                              __nv_bfloat16* __restrict__ Ol) {
    for (int idx = blockIdx.x * blockDim.x + threadIdx.x; idx < 128 * 128;
         idx += gridDim.x * blockDim.x) {
        __nv_bfloat16 h, l;
        bf16_split(W[idx], h, l);
        Oh[idx] = h; Ol[idx] = l;
    }
}

__global__ void prep_w_dual(const float* __restrict__ Wl, const float* __restrict__ Wr,
                            __nv_bfloat16* __restrict__ Oh,
                            __nv_bfloat16* __restrict__ Ol) {
    for (int idx = blockIdx.x * blockDim.x + threadIdx.x; idx < 128 * 256;
         idx += gridDim.x * blockDim.x) {
        int j = idx >> 8, k = idx & 255;
        float w = (k < 128) ? Wl[j * 128 + k] : Wr[j * 128 + (k - 128)];
        __nv_bfloat16 h, l;
        bf16_split(w, h, l);
        Oh[idx] = h; Ol[idx] = l;
    }
}

__global__ void prep_w2_bf16(const float* __restrict__ W2l,
                             const float* __restrict__ W2r) {
    for (int idx = blockIdx.x * blockDim.x + threadIdx.x; idx < 128 * 128;
         idx += gridDim.x * blockDim.x) {
        int j = idx >> 7, k = idx & 127;
        float w = 0.f;
        if (j < 40)      w = W2l[j * 128 + k];
        else if (j < 80) w = W2r[(j - 40) * 128 + k];
        __nv_bfloat16 h, l;
        bf16_split(w, h, l);
        g_w2h[idx] = h; g_w2l[idx] = l;
    }
}

// ---------------- mean aggregation, warp-per-node, float4, MLP8 ----------------
__global__ __launch_bounds__(256)
void agg_mean128_kernel(const float* __restrict__ X,
                        float* __restrict__ OUT, int n) {
    int warp = threadIdx.x >> 5;
    int lane = threadIdx.x & 31;
    int node = blockIdx.x * 8 + warp;
    if (node >= n) return;
    const float4* X4 = (const float4*)X;
    int s0 = g_off[node], s1 = g_off[node + 1];
    float4 a0 = make_float4(0.f, 0.f, 0.f, 0.f);
    float4 a1 = make_float4(0.f, 0.f, 0.f, 0.f);
    for (int base = s0; base < s1; base += 32) {
        int c = s1 - base; if (c > 32) c = 32;
        int nbv = (lane < c) ? g_csr[base + lane] : 0;
        int j = 0;
        for (; j + 8 <= c; j += 8) {
            int v0 = __shfl_sync(0xffffffffu, nbv, j);
            int v1 = __shfl_sync(0xffffffffu, nbv, j + 1);
            int v2 = __shfl_sync(0xffffffffu, nbv, j + 2);
            int v3 = __shfl_sync(0xffffffffu, nbv, j + 3);
            int v4 = __shfl_sync(0xffffffffu, nbv, j + 4);
            int v5 = __shfl_sync(0xffffffffu, nbv, j + 5);
            int v6 = __shfl_sync(0xffffffffu, nbv, j + 6);
            int v7 = __shfl_sync(0xffffffffu, nbv, j + 7);
            float4 x0 = X4[(size_t)v0 * 32 + lane];
            float4 x1 = X4[(size_t)v1 * 32 + lane];
            float4 x2 = X4[(size_t)v2 * 32 + lane];
            float4 x3 = X4[(size_t)v3 * 32 + lane];
            float4 x4 = X4[(size_t)v4 * 32 + lane];
            float4 x5 = X4[(size_t)v5 * 32 + lane];
            float4 x6 = X4[(size_t)v6 * 32 + lane];
            float4 x7 = X4[(size_t)v7 * 32 + lane];
            a0.x += (x0.x + x1.x) + (x2.x + x3.x);
            a0.y += (x0.y + x1.y) + (x2.y + x3.y);
            a0.z += (x0.z + x1.z) + (x2.z + x3.z);
            a0.w += (x0.w + x1.w) + (x2.w + x3.w);
            a1.x += (x4.x + x5.x) + (x6.x + x7.x);
            a1.y += (x4.y + x5.y) + (x6.y + x7.y);
            a1.z += (x4.z + x5.z) + (x6.z + x7.z);
            a1.w += (x4.w + x5.w) + (x6.w + x7.w);
        }
        for (; j < c; j++) {
            int v = __shfl_sync(0xffffffffu, nbv, j);
            float4 x = X4[(size_t)v * 32 + lane];
            a0.x += x.x; a0.y += x.y; a0.z += x.z; a0.w += x.w;
        }
    }
    int deg = s1 - s0;
    float inv = deg > 0 ? 1.f / (float)deg : 0.f;
    float4 acc;
    acc.x = (a0.x + a1.x) * inv;
    acc.y = (a0.y + a1.y) * inv;
    acc.z = (a0.z + a1.z) * inv;
    acc.w = (a0.w + a1.w) * inv;
    ((float4*)OUT)[(size_t)node * 32 + lane] = acc;
}

// ---------------- conv2: agg 40-wide + combine + bias + fused BN2 stats ----------------
__global__ __launch_bounds__(256)
void agg40_kernel(const float* __restrict__ b2, int n) {
    __shared__ float s_sum[40];
    __shared__ float s_sq[40];
    int tid = threadIdx.x;
    if (tid < 40) { s_sum[tid] = 0.f; s_sq[tid] = 0.f; }
    __syncthreads();

    int warp = tid >> 5;
    int lane = tid & 31;
    int node = blockIdx.x * 8 + warp;
    if (node < n) {
        const float4* P4 = (const float4*)g_p;
        int s0 = g_off[node], s1 = g_off[node + 1];
        float4 acc = make_float4(0.f, 0.f, 0.f, 0.f);
        for (int base = s0; base < s1; base += 32) {
            int c = s1 - base; if (c > 32) c = 32;
            int nbv = (lane < c) ? g_csr[base + lane] : 0;
            int j = 0;
            for (; j + 4 <= c; j += 4) {
                int v0 = __shfl_sync(0xffffffffu, nbv, j);
                int v1 = __shfl_sync(0xffffffffu, nbv, j + 1);
                int v2 = __shfl_sync(0xffffffffu, nbv, j + 2);
                int v3 = __shfl_sync(0xffffffffu, nbv, j + 3);
                if (lane < 10) {
                    float4 x0 = P4[(size_t)v0 * 20 + lane];
                    float4 x1 = P4[(size_t)v1 * 20 + lane];
                    float4 x2 = P4[(size_t)v2 * 20 + lane];
                    float4 x3 = P4[(size_t)v3 * 20 + lane];
                    acc.x += (x0.x + x1.x) + (x2.x + x3.x);
                    acc.y += (x0.y + x1.y) + (x2.y + x3.y);
                    acc.z += (x0.z + x1.z) + (x2.z + x3.z);
                    acc.w += (x0.w + x1.w) + (x2.w + x3.w);
                }
            }
            for (; j < c; j++) {
                int v = __shfl_sync(0xffffffffu, nbv, j);
                if (lane < 10) {
                    float4 x = P4[(size_t)v * 20 + lane];
                    acc.x += x.x; acc.y += x.y; acc.z += x.z; acc.w += x.w;
                }
            }
        }
        if (lane < 10) {
            int deg = s1 - s0;
            float inv = deg > 0 ? 1.f / (float)deg : 0.f;
            float4 r  = P4[(size_t)node * 20 + 10 + lane];
            float4 bb = ((const float4*)b2)[lane];
            float4 o;
            o.x = acc.x * inv + r.x + bb.x;
            o.y = acc.y * inv + r.y + bb.y;
            o.z = acc.z * inv + r.z + bb.z;
            o.w = acc.w * inv + r.w + bb.w;
            ((float4*)g_oraw)[(size_t)node * 10 + lane] = o;
            int c0 = lane * 4;
            atomicAdd(&s_sum[c0 + 0], o.x); atomicAdd(&s_sq[c0 + 0], o.x * o.x);
            atomicAdd(&s_sum[c0 + 1], o.y); atomicAdd(&s_sq[c0 + 1], o.y * o.y);
            atomicAdd(&s_sum[c0 + 2], o.z); atomicAdd(&s_sq[c0 + 2], o.z * o.z);
            atomicAdd(&s_sum[c0 + 3], o.w); atomicAdd(&s_sq[c0 + 3], o.w * o.w);
        }
    }
    __syncthreads();
    if (tid < 40) {
        atomicAdd(&g_stats[tid], s_sum[tid]);
        atomicAdd(&g_stats[128 + tid], s_sq[tid]);
    }
}

// ---------------- bf16 mma.sync GEMM with hi/lo split (round-12 exact) ----------------
#define SSTR 40

__device__ __forceinline__ void mma16816(float* c, const uint32_t* a,
                                         uint32_t b0, uint32_t b1) {
    asm volatile(
        "mma.sync.aligned.m16n8k16.row.col.f32.bf16.bf16.f32 "
        "{%0,%1,%2,%3}, {%4,%5,%6,%7}, {%8,%9}, {%0,%1,%2,%3};"
        : "+f"(c[0]), "+f"(c[1]), "+f"(c[2]), "+f"(c[3])
        : "r"(a[0]), "r"(a[1]), "r"(a[2]), "r"(a[3]), "r"(b0), "r"(b1));
}

__global__ __launch_bounds__(256)
void gemm_mma_kernel(const float* __restrict__ A1, const float* __restrict__ A2,
                     const __nv_bfloat16* __restrict__ Bh,
                     const __nv_bfloat16* __restrict__ Bl,
                     const float* __restrict__ bias, const float* __restrict__ addin,
                     float* __restrict__ C, int M, int K, int ncol, int ldc,
                     int relu, int bnA, int do_stats) {
    __shared__ __align__(16) __nv_bfloat16 Ash[128 * SSTR];
    __shared__ __align__(16) __nv_bfloat16 Asl[128 * SSTR];
    __shared__ __align__(16) __nv_bfloat16 Bsh[128 * SSTR];
    __shared__ __align__(16) __nv_bfloat16 Bsl[128 * SSTR];
    __shared__ float s_sum[128];
    __shared__ float s_sq[128];

    const int tid  = threadIdx.x;
    const int wid  = tid >> 5;
    const int lane = tid & 31;
    const int tg   = lane >> 2;
    const int t4   = lane & 3;
    const int wrow = (wid & 3) * 32;
    const int wcol = (wid >> 2) * 64;
    const int row0 = blockIdx.x * 128;

    float acc[2][8][4];
    #pragma unroll
    for (int mt = 0; mt < 2; mt++)
        #pragma unroll
        for (int nt = 0; nt < 8; nt++)
            #pragma unroll
            for (int i = 0; i < 4; i++) acc[mt][nt][i] = 0.f;

    const int sr   = tid >> 1;
    const int shf  = (tid & 1) * 16;

    for (int k0 = 0; k0 < K; k0 += 32) {
        {
            int rg = row0 + sr;
            #pragma unroll
            for (int i = 0; i < 4; i++) {
                int kg = k0 + shf + i * 4;
                const float* Ap = (kg < 128) ? A1 : A2;
                int kl = kg & 127;
                float4 v = make_float4(0.f, 0.f, 0.f, 0.f);
                if (rg < M) v = *(const float4*)&Ap[(size_t)rg * 128 + kl];
                if (bnA) {
                    float4 sc = *(const float4*)&g_scale[kg];
                    float4 sh = *(const float4*)&g_shift[kg];
                    v.x = fmaxf(v.x * sc.x + sh.x, 0.f);
                    v.y = fmaxf(v.y * sc.y + sh.y, 0.f);
                    v.z = fmaxf(v.z * sc.z + sh.z, 0.f);
                    v.w = fmaxf(v.w * sc.w + sh.w, 0.f);
                }
                __nv_bfloat16 hx = __float2bfloat16(v.x);
                __nv_bfloat16 hy = __float2bfloat16(v.y);
                __nv_bfloat16 hz = __float2bfloat16(v.z);
                __nv_bfloat16 hw = __float2bfloat16(v.w);
                __nv_bfloat16 lx = __float2bfloat16(v.x - __bfloat162float(hx));
                __nv_bfloat16 ly = __float2bfloat16(v.y - __bfloat162float(hy));
                __nv_bfloat16 lz = __float2bfloat16(v.z - __bfloat162float(hz));
                __nv_bfloat16 lw = __float2bfloat16(v.w - __bfloat162float(hw));
                uint32_t* dh = (uint32_t*)&Ash[sr * SSTR + shf + i * 4];
                uint32_t* dl = (uint32_t*)&Asl[sr * SSTR + shf + i * 4];
                dh[0] = (uint32_t)__bfloat16_as_ushort(hx) |
                        ((uint32_t)__bfloat16_as_ushort(hy) << 16);
                dh[1] = (uint32_t)__bfloat16_as_ushort(hz) |
                        ((uint32_t)__bfloat16_as_ushort(hw) << 16);
                dl[0] = (uint32_t)__bfloat16_as_ushort(lx) |
                        ((uint32_t)__bfloat16_as_ushort(ly) << 16);
                dl[1] = (uint32_t)__bfloat16_as_ushort(lz) |
                        ((uint32_t)__bfloat16_as_ushort(lw) << 16);
            }
        }
        {
            const uint4* sh_ = (const uint4*)&Bh[(size_t)sr * K + k0 + shf];
            const uint4* sl_ = (const uint4*)&Bl[(size_t)sr * K + k0 + shf];
            uint4* dh = (uint4*)&Bsh[sr * SSTR + shf];
            uint4* dl = (uint4*)&Bsl[sr * SSTR + shf];
            dh[0] = sh_[0]; dh[1] = sh_[1];
            dl[0] = sl_[0]; dl[1] = sl_[1];
        }
        __syncthreads();

        #pragma unroll
        for (int s = 0; s < 2; s++) {
            const int kb = s * 16;
            uint32_t ah[2][4], al[2][4];
            #pragma unroll
            for (int mt = 0; mt < 2; mt++) {
                int r = wrow + 16 * mt + tg;
                int o0 = r * SSTR + kb + t4 * 2;
                int o1 = (r + 8) * SSTR + kb + t4 * 2;
                ah[mt][0] = *(const uint32_t*)&Ash[o0];
                ah[mt][1] = *(const uint32_t*)&Ash[o1];
                ah[mt][2] = *(const uint32_t*)&Ash[o0 + 8];
                ah[mt][3] = *(const uint32_t*)&Ash[o1 + 8];
                al[mt][0] = *(const uint32_t*)&Asl[o0];
                al[mt][1] = *(const uint32_t*)&Asl[o1];
                al[mt][2] = *(const uint32_t*)&Asl[o0 + 8];
                al[mt][3] = *(const uint32_t*)&Asl[o1 + 8];
            }
            #pragma unroll
            for (int nt = 0; nt < 8; nt++) {
                int bn = wcol + 8 * nt + tg;
                int ob = bn * SSTR + kb + t4 * 2;
                uint32_t bh0 = *(const uint32_t*)&Bsh[ob];
                uint32_t bh1 = *(const uint32_t*)&Bsh[ob + 8];
                uint32_t bl0 = *(const uint32_t*)&Bsl[ob];
                uint32_t bl1 = *(const uint32_t*)&Bsl[ob + 8];
                #pragma unroll
                for (int mt = 0; mt < 2; mt++) {
                    mma16816(acc[mt][nt], ah[mt], bh0, bh1);
                    mma16816(acc[mt][nt], al[mt], bh0, bh1);
                    mma16816(acc[mt][nt], ah[mt], bl0, bl1);
                }
            }
        }
        __syncthreads();
    }

    // ---- epilogue ----
    float colsum[8][2], colsq[8][2];
    #pragma unroll
    for (int nt = 0; nt < 8; nt++) {
        colsum[nt][0] = 0.f; colsum[nt][1] = 0.f;
        colsq[nt][0] = 0.f;  colsq[nt][1] = 0.f;
    }

    #pragma unroll
    for (int mt = 0; mt < 2; mt++) {
        #pragma unroll
        for (int half = 0; half < 2; half++) {
            int rg = row0 + wrow + 16 * mt + tg + 8 * half;
            bool rok = rg < M;
            #pragma unroll
            for (int nt = 0; nt < 8; nt++) {
                int c = wcol + 8 * nt + 2 * t4;
                if (c >= ncol) continue;
                float v0 = acc[mt][nt][2 * half + 0];
                float v1 = acc[mt][nt][2 * half + 1];
                if (bias) {
                    float2 bb = *(const float2*)&bias[c];
                    v0 += bb.x; v1 += bb.y;
                }
                if (rok) {
                    if (addin) {
                        float2 aa = *(const float2*)&addin[(size_t)rg * ldc + c];
                        v0 += aa.x; v1 += aa.y;
                    }
                    if (relu) { v0 = fmaxf(v0, 0.f); v1 = fmaxf(v1, 0.f); }
                    *(float2*)&C[(size_t)rg * ldc + c] = make_float2(v0, v1);
                    if (do_stats) {
                        colsum[nt][0] += v0; colsum[nt][1] += v1;
                        colsq[nt][0] += v0 * v0; colsq[nt][1] += v1 * v1;
                    }
                }
            }
        }
    }

    if (do_stats) {
        if (tid < 128) { s_sum[tid] = 0.f; s_sq[tid] = 0.f; }
        __syncthreads();
        #pragma unroll
        for (int nt = 0; nt < 8; nt++) {
            int c = wcol + 8 * nt + 2 * t4;
            if (c < ncol) {
                atomicAdd(&s_sum[c],     colsum[nt][0]);
                atomicAdd(&s_sum[c + 1], colsum[nt][1]);
                atomicAdd(&s_sq[c],      colsq[nt][0]);
                atomicAdd(&s_sq[c + 1],  colsq[nt][1]);
            }
        }
        __syncthreads();
        if (tid < 128) {
            atomicAdd(&g_stats[tid], s_sum[tid]);
            atomicAdd(&g_stats[128 + tid], s_sq[tid]);
        }
    }
}

// ---------------- BatchNorm helpers ----------------
__global__ void zero_stats_kernel() {
    if (threadIdx.x < 256) g_stats[threadIdx.x] = 0.f;
}

// reads stats, writes scale/shift, then zeroes stats for the next use
__global__ void bn_finalize_kernel(const float* __restrict__ gamma,
                                   const float* __restrict__ beta,
                                   int F, float invM) {
    int c = threadIdx.x;
    if (c < F) {
        float mu  = g_stats[c] * invM;
        float var = g_stats[128 + c] * invM - mu * mu;
        float sc  = gamma[c] * rsqrtf(var + BN_EPS);
        g_scale[c] = sc;
        g_shift[c] = beta[c] - mu * sc;
        g_stats[c] = 0.f;
        g_stats[128 + c] = 0.f;
    }
}

__global__ void bn_apply_kernel(const float* __restrict__ X, float* __restrict__ Y,
                                int total, int F) {
    for (int i = blockIdx.x * blockDim.x + threadIdx.x; i < total;
         i += gridDim.x * blockDim.x) {
        int c = i % F;
        Y[i] = X[i] * g_scale[c] + g_shift[c];
    }
}

// ---------------- launcher ----------------
extern "C" void kernel_launch(void* const* d_in, const int* in_sizes, int n_in,
                              void* d_out, int out_size) {
    const float* x   = (const float*)d_in[0];
    const void*  ei  = d_in[1];
    const float* W1l = (const float*)d_in[2];
    const float* b1  = (const float*)d_in[3];
    const float* W1r = (const float*)d_in[4];
    const float* Wxl = (const float*)d_in[5];
    const float* bx  = (const float*)d_in[6];
    const float* Wxr = (const float*)d_in[7];
    const float* W2l = (const float*)d_in[8];
    const float* b2  = (const float*)d_in[9];
    const float* W2r = (const float*)d_in[10];
    const float* g3  = (const float*)d_in[11];
    const float* be3 = (const float*)d_in[12];
    const float* g2  = (const float*)d_in[13];
    const float* be2 = (const float*)d_in[14];
    float* out = (float*)d_out;

    const int N    = in_sizes[0] / NF;
    const int twoE = in_sizes[1];
    const int E    = twoE / 2;

    float *p_agg, *p_h1, *p_h2, *p_p, *p_oraw;
    int   *p_deg;
    __nv_bfloat16 *w1rh, *w1rl, *w1lh, *w1ll, *wxh, *wxl, *w2h, *w2l;
    cudaGetSymbolAddress((void**)&p_agg,  g_agg);
    cudaGetSymbolAddress((void**)&p_h1,   g_h1);
    cudaGetSymbolAddress((void**)&p_h2,   g_h2);
    cudaGetSymbolAddress((void**)&p_p,    g_p);
    cudaGetSymbolAddress((void**)&p_oraw, g_oraw);
    cudaGetSymbolAddress((void**)&p_deg,  g_deg);
    cudaGetSymbolAddress((void**)&w1rh, g_w1rh); cudaGetSymbolAddress((void**)&w1rl, g_w1rl);
    cudaGetSymbolAddress((void**)&w1lh, g_w1lh); cudaGetSymbolAddress((void**)&w1ll, g_w1ll);
    cudaGetSymbolAddress((void**)&wxh,  g_wxh);  cudaGetSymbolAddress((void**)&wxl,  g_wxl);
    cudaGetSymbolAddress((void**)&w2h,  g_w2h);  cudaGetSymbolAddress((void**)&w2l,  g_w2l);

    const int nb = (N + 511) / 512;
    const int gemm_blocks = (N + 127) / 128;
    const int agg_blocks  = (N + 7) / 8;

    cudaStream_t s2;
    cudaStreamCreateWithFlags(&s2, cudaStreamNonBlocking);
    cudaEvent_t evA, evB;
    cudaEventCreateWithFlags(&evA, cudaEventDisableTiming);
    cudaEventCreateWithFlags(&evB, cudaEventDisableTiming);

    // --- fork: CSR chain on s2 ---
    detect_dtype_kernel<<<1, 32>>>(ei, E, N);
    cudaEventRecord(evA, 0);
    cudaStreamWaitEvent(s2, evA, 0);

    zero_int_kernel<<<512, 256, 0, s2>>>(p_deg, N);
    count_deg_direct<<<2048, 256, 0, s2>>>(ei, E);
    scan1_kernel<<<nb, 512, 0, s2>>>(N);
    scan2_kernel<<<1, 256, 0, s2>>>(nb);
    scan3_kernel<<<512, 256, 0, s2>>>(N);
    fill_csr_direct<<<2048, 256, 0, s2>>>(ei, E);
    cudaEventRecord(evB, s2);

    // --- main: weight prep + conv1a (x @ W1r^T + b1) + stats zero (hoisted) ---
    prep_w_single<<<64, 256>>>(W1r, w1rh, w1rl);
    zero_stats_kernel<<<1, 256>>>();
    gemm_mma_kernel<<<gemm_blocks, 256>>>(x, x, w1rh, w1rl, b1, nullptr,
                                          p_h1, N, 128, 128, 128, 0, 0, 0);
    prep_w_single<<<64, 256>>>(W1l, w1lh, w1ll);
    prep_w_dual<<<128, 256>>>(Wxl, Wxr, wxh, wxl);
    prep_w2_bf16<<<64, 256>>>(W2l, W2r);

    // --- join CSR ---
    cudaStreamWaitEvent(0, evB, 0);

    // conv1 part 2: h1 = relu(agg @ W1l^T + h1)
    agg_mean128_kernel<<<agg_blocks, 256>>>(x, p_agg, N);
    gemm_mma_kernel<<<gemm_blocks, 256>>>(p_agg, p_agg, w1lh, w1ll, nullptr, p_h1,
                                          p_h1, N, 128, 128, 128, 1, 0, 0);

    // convx: h2 = concat(agg, h1) @ [Wxl|Wxr]^T + bx  (+BN3 stats fused)
    agg_mean128_kernel<<<agg_blocks, 256>>>(p_h1, p_agg, N);
    gemm_mma_kernel<<<gemm_blocks, 256>>>(p_agg, p_h1, wxh, wxl, bx, nullptr,
                                          p_h2, N, 256, 128, 128, 0, 0, 1);
    bn_finalize_kernel<<<1, 128>>>(g3, be3, 128, 1.f / (float)N);  // also zeroes stats

    // conv2 projection: P = BNrelu(h2) @ [W2l|W2r]^T  (bnA fused)
    gemm_mma_kernel<<<gemm_blocks, 256>>>(p_h2, p_h2, w2h, w2l, nullptr, nullptr,
                                          p_p, N, 128, 80, 80, 0, 1, 0);
    // aggregate + combine + BN2 stats
    agg40_kernel<<<agg_blocks, 256>>>(b2, N);

    // BN2 -> output
    bn_finalize_kernel<<<1, 64>>>(g2, be2, NCLASS, 1.f / (float)N);
    bn_apply_kernel<<<2048, 256>>>(p_oraw, out, N * NCLASS, NCLASS);
}